// round 16
// baseline (speedup 1.0000x reference)
#include <cuda_runtime.h>
#include <cstdint>

#define HEADS 4
#define HD 32
#define NTOK 98
#define CDIM 128

static __device__ __constant__ float SCALE_C = 0.17677669529663687f; // 32^-0.5

// Scratch (device globals; no allocation allowed). Layout: [m][128] row-contig.
__device__ float g_q[(size_t)2048 * NTOK * CDIM];
__device__ float g_k[(size_t)2048 * NTOK * CDIM];
__device__ float g_v[(size_t)2048 * NTOK * CDIM];
__device__ float g_o[(size_t)2048 * NTOK * CDIM];

// Pre-converted (tf32) + fragment-permuted weights: 4 tiles (qkv0,1,2, proj),
// 2 K-halves each, 8704 floats per (tile,half).
__device__ float g_wperm[4 * 2 * 8704];

__device__ __forceinline__ uint32_t f2tf(float f) {
    uint32_t u;
    asm("cvt.rna.tf32.f32 %0, %1;" : "=r"(u) : "f"(f));
    return u;
}

__device__ __forceinline__ void mma_tf32(float c[4], uint32_t a0, uint32_t a1,
                                         uint32_t a2, uint32_t a3,
                                         uint32_t b0, uint32_t b1) {
    asm volatile(
        "mma.sync.aligned.m16n8k8.row.col.f32.tf32.tf32.f32 "
        "{%0,%1,%2,%3}, {%4,%5,%6,%7}, {%8,%9}, {%0,%1,%2,%3};"
        : "+f"(c[0]), "+f"(c[1]), "+f"(c[2]), "+f"(c[3])
        : "r"(a0), "r"(a1), "r"(a2), "r"(a3), "r"(b0), "r"(b1));
}

__device__ __forceinline__ uint32_t smem_u32(const void* p) {
    uint32_t a;
    asm("{ .reg .u64 t; cvta.to.shared.u64 t, %1; cvt.u32.u64 %0, t; }"
        : "=r"(a) : "l"(p));
    return a;
}

__device__ __forceinline__ void cpa16(uint32_t dst, const void* src) {
    asm volatile("cp.async.cg.shared.global [%0], [%1], 16;"
                 :: "r"(dst), "l"(src) : "memory");
}

// ---------------- weight prep: tf32 convert + permute ----------------
// Layout per (tile,half): idx(n 0..127, k 0..63) =
//   (n>>3)*8*68 + (k>>3)*68 + ((n&7)*4 + (k&3))*2 + ((k>>2)&1)
__global__ void prep_w(const float* __restrict__ qkv_w,
                       const float* __restrict__ proj_w)
{
    int e = blockIdx.x * 256 + threadIdx.x;     // 0..65535
    int wrow = e >> 7, kg = e & 127;
    int tile, n;
    const float* src;
    if (wrow < 384) { tile = wrow >> 7; n = wrow & 127; src = qkv_w + (size_t)wrow * 128; }
    else            { tile = 3;         n = wrow & 127; src = proj_w + (size_t)n * 128; }
    int half = kg >> 6, k = kg & 63;
    int dst = (tile * 2 + half) * 8704
            + ((n >> 3) * 8 + (k >> 3)) * 68
            + (((n & 7) * 4 + (k & 3)) << 1) + ((k >> 2) & 1);
    ((uint32_t*)g_wperm)[dst] = f2tf(src[kg]);
}

// ---------------- tf32 mma.sync GEMM: A from gmem, B via cp.async pipeline ----
// C[M, ntiles*128] = A[M,128] @ W[ntiles*128,128]^T + bias
#define BS_F 8704
#define GEMM_SMEM (2 * BS_F * 4)    // 69632 B

__global__ __launch_bounds__(256, 2)
void gemm_mma(const float* __restrict__ A,
              const float* __restrict__ bias,
              float* __restrict__ Cout,
              int ntiles, int epi)
{
    extern __shared__ float smf[];
    uint32_t sb = smem_u32(smf);

    int tid = threadIdx.x;
    int w = tid >> 5, l = tid & 31;
    int g = l >> 2, t4 = l & 3;
    int wm = w >> 1, wn = w & 1;       // 4 x 2 warp grid
    int m0 = blockIdx.x * 128;

    const float* Ap = (epi == 1) ? (const float*)g_o : A;
    const float* wsrc = g_wperm + (epi == 1 ? 3 * 2 * 8704 : 0);

    int S = ntiles * 2;

    // prologue: stage 0 -> buf 0
    {
        const float4* src = (const float4*)(wsrc);
        for (int i = tid; i < 2176; i += 256)
            cpa16(sb + (uint32_t)i * 16u, src + i);
        asm volatile("cp.async.commit_group;" ::: "memory");
    }

    float c[2][8][4];

    for (int s = 0; s < S; s++) {
        int nt = s >> 1, half = s & 1;
        if (half == 0) {
            #pragma unroll
            for (int mi = 0; mi < 2; mi++)
                #pragma unroll
                for (int ni = 0; ni < 8; ni++)
                    #pragma unroll
                    for (int q = 0; q < 4; q++) c[mi][ni][q] = 0.f;
        }
        if (s + 1 < S) {
            const float4* src = (const float4*)(wsrc + (size_t)(s + 1) * BS_F);
            uint32_t dbase = sb + (uint32_t)(((s + 1) & 1) * BS_F * 4);
            for (int i = tid; i < 2176; i += 256)
                cpa16(dbase + (uint32_t)i * 16u, src + i);
            asm volatile("cp.async.commit_group;" ::: "memory");
            asm volatile("cp.async.wait_group 1;" ::: "memory");
        } else {
            asm volatile("cp.async.wait_group 0;" ::: "memory");
        }
        __syncthreads();

        const uint32_t* B2 = (const uint32_t*)(smf + (s & 1) * BS_F);
        const float* arow0 = Ap + (size_t)(m0 + wm * 32 + g) * 128 + half * 64 + t4;

        #pragma unroll
        for (int ks = 0; ks < 8; ks++) {
            uint32_t a[2][4];
            #pragma unroll
            for (int mi = 0; mi < 2; mi++) {
                const float* ar = arow0 + mi * (16 * 128) + ks * 8;
                a[mi][0] = f2tf(ar[0]);
                a[mi][1] = f2tf(ar[8 * 128]);
                a[mi][2] = f2tf(ar[4]);
                a[mi][3] = f2tf(ar[8 * 128 + 4]);
            }
            #pragma unroll
            for (int ni = 0; ni < 8; ni++) {
                uint2 bv = *(const uint2*)(B2 + (((wn * 8 + ni) * 8 + ks) * 68
                                                + ((g * 4 + t4) << 1)));
                #pragma unroll
                for (int mi = 0; mi < 2; mi++)
                    mma_tf32(c[mi][ni], a[mi][0], a[mi][1], a[mi][2], a[mi][3],
                             bv.x, bv.y);
            }
        }
        __syncthreads();

        if (half == 1) {
            // Epilogue for tile nt: fused bias (+scale), float2 stores
            float* dst;
            const float* bp;
            float sc;
            if (epi == 0) {
                dst = (nt == 0) ? g_q : (nt == 1) ? g_k : g_v;
                bp = bias + nt * 128;
                sc = (nt == 0) ? SCALE_C : 1.0f;
            } else {
                dst = Cout;
                bp = bias;
                sc = 1.0f;
            }
            #pragma unroll
            for (int ni = 0; ni < 8; ni++) {
                int col = wn * 64 + ni * 8 + t4 * 2;
                float2 b2 = *(const float2*)(bp + col);
                #pragma unroll
                for (int mi = 0; mi < 2; mi++) {
                    int row0 = wm * 32 + mi * 16 + g;
                    float2 s0, s1;
                    s0.x = (c[mi][ni][0] + b2.x) * sc;
                    s0.y = (c[mi][ni][1] + b2.y) * sc;
                    s1.x = (c[mi][ni][2] + b2.x) * sc;
                    s1.y = (c[mi][ni][3] + b2.y) * sc;
                    *(float2*)&dst[(size_t)(m0 + row0) * 128 + col] = s0;
                    *(float2*)&dst[(size_t)(m0 + row0 + 8) * 128 + col] = s1;
                }
            }
        }
    }
}

// ---------------- tensor-core attention, register-resident P ----------------
// One block per (window b, head h). 7 warps; warp w owns S rows 16w..16w+15.
// S accumulators seeded with bias+mask BEFORE the QK mma (hides mask LDG).
// smem (floats): qs 112*36, ks 112*36, vt 32*116, bias 507 = 49 KB
#define ATQ_OFF 0
#define ATK_OFF 4032
#define ATV_OFF 8064
#define ATB_OFF 11776
#define AT_FLOATS 12283

__global__ __launch_bounds__(224, 3)
void attn_mma(const float* __restrict__ rel,
              const float* __restrict__ mask,
              int L)
{
    extern __shared__ float sm[];
    uint32_t* qs = (uint32_t*)sm + ATQ_OFF;   // tf32 bits, stride 36
    uint32_t* ks = (uint32_t*)sm + ATK_OFF;   // stride 36
    uint32_t* vt = (uint32_t*)sm + ATV_OFF;   // v transposed [d][j], stride 116
    float*    bs = sm + ATB_OFF;              // 507

    int tid = threadIdx.x;
    int bh = blockIdx.x;
    int b = bh >> 2;
    int h = bh & 3;
    int w = tid >> 5, l = tid & 31;
    int g = l >> 2, t4 = l & 3;

    size_t rowbase = (size_t)(b * NTOK) * CDIM + h * HD;

    // Stage q, k (tf32) and v transposed
    #pragma unroll
    for (int it = 0; it < 14; it++) {
        int idx = tid + it * 224;
        int r = idx >> 5, c = idx & 31;
        float qv = g_q[rowbase + (size_t)r * CDIM + c];
        float kv = g_k[rowbase + (size_t)r * CDIM + c];
        float vv = g_v[rowbase + (size_t)r * CDIM + c];
        qs[r * 36 + c] = f2tf(qv);
        ks[r * 36 + c] = f2tf(kv);
        vt[c * 116 + r] = f2tf(vv);           // [d][j]
    }
    // zero padded q/k rows 98..111 (S-mma reads them; seeds rely on +0)
    for (int idx = tid; idx < 14 * 32; idx += 224) {
        int r = 98 + (idx >> 5), c = idx & 31;
        qs[r * 36 + c] = 0u;
        ks[r * 36 + c] = 0u;
    }
    // zero v padded cols j=98..115
    for (int idx = tid; idx < 32 * 18; idx += 224) {
        int d = idx / 18, j = 98 + idx % 18;
        vt[d * 116 + j] = 0u;
    }
    for (int idx = tid; idx < 507; idx += 224) bs[idx] = rel[h * 507 + idx];
    __syncthreads();

    const float* mrow = mask + (size_t)(b % L) * (NTOK * NTOK);

    int i0 = w * 16;
    int iA = i0 + g, iB = iA + 8;

    // ---- seed accumulators with bias + mask (pre-mma; LDG hidden by mma) ----
    float c[14][4];
    int tiA = iA / 49, riA = iA - tiA * 49, hiA = riA / 7, wiA = riA - hiA * 7;
    int tiB = iB / 49, riB = iB - tiB * 49, hiB = riB / 7, wiB = riB - hiB * 7;
    #pragma unroll
    for (int ni = 0; ni < 14; ni++) {
        int j0 = ni * 8 + t4 * 2;
        if (j0 < NTOK) {
            int tj0 = j0 / 49, rj0 = j0 - tj0 * 49, hj0 = rj0 / 7, wj0 = rj0 - hj0 * 7;
            int j1 = j0 + 1;
            int tj1 = j1 / 49, rj1 = j1 - tj1 * 49, hj1 = rj1 / 7, wj1 = rj1 - hj1 * 7;
            if (iA < NTOK) {
                float2 mv = *(const float2*)&mrow[iA * NTOK + j0];
                c[ni][0] = bs[(tiA - tj0 + 1) * 169 + (hiA - hj0 + 6) * 13 + (wiA - wj0 + 6)] + mv.x;
                c[ni][1] = bs[(tiA - tj1 + 1) * 169 + (hiA - hj1 + 6) * 13 + (wiA - wj1 + 6)] + mv.y;
            } else { c[ni][0] = -1e30f; c[ni][1] = -1e30f; }
            if (iB < NTOK) {
                float2 mv = *(const float2*)&mrow[iB * NTOK + j0];
                c[ni][2] = bs[(tiB - tj0 + 1) * 169 + (hiB - hj0 + 6) * 13 + (wiB - wj0 + 6)] + mv.x;
                c[ni][3] = bs[(tiB - tj1 + 1) * 169 + (hiB - hj1 + 6) * 13 + (wiB - wj1 + 6)] + mv.y;
            } else { c[ni][2] = -1e30f; c[ni][3] = -1e30f; }
        } else {
            c[ni][0] = -1e30f; c[ni][1] = -1e30f;
            c[ni][2] = -1e30f; c[ni][3] = -1e30f;
        }
    }

    // ---- S += q @ k^T via mma (padded rows contribute exact 0) ----
    {
        const uint32_t* ab = qs + (size_t)iA * 36 + t4;
        const uint32_t* bb = ks + (size_t)g * 36 + t4;
        #pragma unroll
        for (int k0 = 0; k0 < 32; k0 += 8) {
            uint32_t a0 = ab[k0], a1 = ab[8 * 36 + k0];
            uint32_t a2 = ab[k0 + 4], a3 = ab[8 * 36 + k0 + 4];
            #pragma unroll
            for (int ni = 0; ni < 14; ni++) {
                uint32_t b0 = bb[ni * 8 * 36 + k0];
                uint32_t b1 = bb[ni * 8 * 36 + k0 + 4];
                mma_tf32(c[ni], a0, a1, a2, a3, b0, b1);
            }
        }
    }

    // ---- softmax in registers (row = 4-lane quad) ----
    float m0 = -1e30f, m1 = -1e30f;
    #pragma unroll
    for (int ni = 0; ni < 14; ni++) {
        m0 = fmaxf(m0, fmaxf(c[ni][0], c[ni][1]));
        m1 = fmaxf(m1, fmaxf(c[ni][2], c[ni][3]));
    }
    m0 = fmaxf(m0, __shfl_xor_sync(0xFFFFFFFFu, m0, 1));
    m0 = fmaxf(m0, __shfl_xor_sync(0xFFFFFFFFu, m0, 2));
    m1 = fmaxf(m1, __shfl_xor_sync(0xFFFFFFFFu, m1, 1));
    m1 = fmaxf(m1, __shfl_xor_sync(0xFFFFFFFFu, m1, 2));
    float s0 = 0.f, s1 = 0.f;
    #pragma unroll
    for (int ni = 0; ni < 14; ni++) {
        c[ni][0] = __expf(c[ni][0] - m0);
        c[ni][1] = __expf(c[ni][1] - m0);
        c[ni][2] = __expf(c[ni][2] - m1);
        c[ni][3] = __expf(c[ni][3] - m1);
        s0 += c[ni][0] + c[ni][1];
        s1 += c[ni][2] + c[ni][3];
    }
    s0 += __shfl_xor_sync(0xFFFFFFFFu, s0, 1);
    s0 += __shfl_xor_sync(0xFFFFFFFFu, s0, 2);
    s1 += __shfl_xor_sync(0xFFFFFFFFu, s1, 1);
    s1 += __shfl_xor_sync(0xFFFFFFFFu, s1, 2);
    float inv0 = (iA < NTOK) ? (1.f / s0) : 0.f;   // padded rows -> P = 0
    float inv1 = (iB < NTOK) ? (1.f / s1) : 0.f;

    #pragma unroll
    for (int ni = 0; ni < 14; ni++) {
        c[ni][0] *= inv0; c[ni][1] *= inv0;
        c[ni][2] *= inv1; c[ni][3] *= inv1;
    }

    // ---- O = P @ v via mma; P C-frag -> A-frag via intra-quad shuffles ----
    float o[4][4];
    #pragma unroll
    for (int ni = 0; ni < 4; ni++)
        #pragma unroll
        for (int q = 0; q < 4; q++) o[ni][q] = 0.f;

    {
        int qb = l & ~3;
        int srcLo = qb + (t4 >> 1);        // owner of col t4   (pair t4>>1)
        int srcHi = qb + 2 + (t4 >> 1);    // owner of col t4+4
        bool odd = (t4 & 1) != 0;
        const uint32_t* bb = vt + (size_t)g * 116 + t4;
        #pragma unroll
        for (int kk = 0; kk < 14; kk++) {
            float s0a = __shfl_sync(0xFFFFFFFFu, c[kk][0], srcLo);
            float s0b = __shfl_sync(0xFFFFFFFFu, c[kk][1], srcLo);
            float s2a = __shfl_sync(0xFFFFFFFFu, c[kk][0], srcHi);
            float s2b = __shfl_sync(0xFFFFFFFFu, c[kk][1], srcHi);
            float s1a = __shfl_sync(0xFFFFFFFFu, c[kk][2], srcLo);
            float s1b = __shfl_sync(0xFFFFFFFFu, c[kk][3], srcLo);
            float s3a = __shfl_sync(0xFFFFFFFFu, c[kk][2], srcHi);
            float s3b = __shfl_sync(0xFFFFFFFFu, c[kk][3], srcHi);
            uint32_t a0 = f2tf(odd ? s0b : s0a);   // P[iA][8kk+t4]
            uint32_t a1 = f2tf(odd ? s1b : s1a);   // P[iB][8kk+t4]
            uint32_t a2 = f2tf(odd ? s2b : s2a);   // P[iA][8kk+t4+4]
            uint32_t a3 = f2tf(odd ? s3b : s3a);   // P[iB][8kk+t4+4]
            int k0 = kk * 8;
            #pragma unroll
            for (int ni = 0; ni < 4; ni++) {
                uint32_t b0 = bb[ni * 8 * 116 + k0];
                uint32_t b1 = bb[ni * 8 * 116 + k0 + 4];
                mma_tf32(o[ni], a0, a1, a2, a3, b0, b1);
            }
        }
    }

    // write O (rows < 98 only)
    #pragma unroll
    for (int ni = 0; ni < 4; ni++) {
        int d0 = ni * 8 + t4 * 2;
        if (iA < NTOK) {
            float2 s; s.x = o[ni][0]; s.y = o[ni][1];
            *(float2*)&g_o[rowbase + (size_t)iA * CDIM + d0] = s;
        }
        if (iB < NTOK) {
            float2 s; s.x = o[ni][2]; s.y = o[ni][3];
            *(float2*)&g_o[rowbase + (size_t)iB * CDIM + d0] = s;
        }
    }
}

extern "C" void kernel_launch(void* const* d_in, const int* in_sizes, int n_in,
                              void* d_out, int out_size)
{
    const float* x      = (const float*)d_in[0];
    const float* mask   = (const float*)d_in[1];
    const float* qkv_w  = (const float*)d_in[2];
    const float* qkv_b  = (const float*)d_in[3];
    const float* rel    = (const float*)d_in[4];
    const float* proj_w = (const float*)d_in[5];
    const float* proj_b = (const float*)d_in[6];
    float* out = (float*)d_out;

    int B = in_sizes[0] / (NTOK * CDIM);        // 2048
    int L = in_sizes[1] / (NTOK * NTOK);        // 512
    int M = B * NTOK;                            // 200704

    cudaFuncSetAttribute(gemm_mma, cudaFuncAttributeMaxDynamicSharedMemorySize, GEMM_SMEM);
    const int attn_smem = AT_FLOATS * (int)sizeof(float);   // 49132
    cudaFuncSetAttribute(attn_mma, cudaFuncAttributeMaxDynamicSharedMemorySize, attn_smem);

    prep_w<<<256, 256>>>(qkv_w, proj_w);

    gemm_mma<<<M / 128, 256, GEMM_SMEM>>>(x, qkv_b, nullptr, 3, 0);

    attn_mma<<<B * HEADS, 224, attn_smem>>>(rel, mask, L);

    gemm_mma<<<M / 128, 256, GEMM_SMEM>>>(nullptr, proj_b, out, 1, 1);
}